// round 10
// baseline (speedup 1.0000x reference)
#include <cuda_runtime.h>
#include <cuda_fp16.h>
#include <cstdint>

#define BATCH 32768
#define NCH   256
#define FLAT  3072
#define NRED  152
#define NBLK_MOM 128
#define EPSV  1e-5f

// ---------------- device scratch ----------------
__device__ float g_part[NBLK_MOM][NRED];
__device__ float g_wscaled[NCH * 16];
__device__ float g_shift[NCH];
// fc1 weights fp16 (hi only), layout [k'][n], k' = p*256 + c
__device__ __half g_w1hi[FLAT * 128];

// ======================= PTX helpers ==================
__device__ __forceinline__ uint32_t smem_u32(const void* p) {
    uint32_t a;
    asm("{ .reg .u64 t; cvta.to.shared.u64 t, %1; cvt.u32.u64 %0, t; }"
        : "=r"(a) : "l"(p));
    return a;
}
#define CP_ASYNC16(dst, src) \
    asm volatile("cp.async.cg.shared.global [%0], [%1], 16;" \
        :: "r"(dst), "l"(src) : "memory")
#define CP_COMMIT() asm volatile("cp.async.commit_group;" ::: "memory")
#define CP_WAIT1()  asm volatile("cp.async.wait_group 1;" ::: "memory")
#define CP_WAIT0()  asm volatile("cp.async.wait_group 0;" ::: "memory")

__device__ __forceinline__ void ldsm_x4t(uint32_t r[4], uint32_t addr) {
    asm volatile("ldmatrix.sync.aligned.m8n8.x4.trans.shared.b16 {%0,%1,%2,%3}, [%4];"
        : "=r"(r[0]), "=r"(r[1]), "=r"(r[2]), "=r"(r[3]) : "r"(addr));
}
__device__ __forceinline__ void mma16816(float& d0, float& d1, float& d2, float& d3,
                                         uint32_t a0, uint32_t a1, uint32_t a2, uint32_t a3,
                                         uint32_t b0, uint32_t b1) {
    asm volatile(
        "mma.sync.aligned.m16n8k16.row.col.f32.f16.f16.f32 "
        "{%0,%1,%2,%3}, {%4,%5,%6,%7}, {%8,%9}, {%0,%1,%2,%3};"
        : "+f"(d0), "+f"(d1), "+f"(d2), "+f"(d3)
        : "r"(a0), "r"(a1), "r"(a2), "r"(a3), "r"(b0), "r"(b1));
}
__device__ __forceinline__ uint32_t f2h2(float a, float b) {
    __half2 h = __floats2half2_rn(a, b);
    return *reinterpret_cast<uint32_t*>(&h);
}

// =========================================================================
// K1: patch moments (proven)
// =========================================================================
__global__ void k_moments(const float* __restrict__ x)
{
    int b = blockIdx.x * 256 + threadIdx.x;
    const float* xb = x + b * 42;
    float xv[42];
#pragma unroll
    for (int i = 0; i < 42; i++) xv[i] = xb[i];

    __shared__ float red[8][NRED];
    int lane = threadIdx.x & 31;
    int warp = threadIdx.x >> 5;

    int idx = 0;
#pragma unroll
    for (int k = 0; k < 16; k++) {
        float s = 0.f;
#pragma unroll
        for (int r = 0; r < 3; r++)
#pragma unroll
            for (int c = 0; c < 4; c++)
                s += xv[(r + (k >> 2)) * 7 + (c + (k & 3))];
#pragma unroll
        for (int o = 16; o; o >>= 1) s += __shfl_xor_sync(0xffffffffu, s, o);
        if (lane == 0) red[warp][idx] = s;
        idx++;
    }
#pragma unroll
    for (int k = 0; k < 16; k++) {
#pragma unroll
        for (int l = k; l < 16; l++) {
            float s = 0.f;
#pragma unroll
            for (int r = 0; r < 3; r++)
#pragma unroll
                for (int c = 0; c < 4; c++)
                    s += xv[(r + (k >> 2)) * 7 + (c + (k & 3))] *
                         xv[(r + (l >> 2)) * 7 + (c + (l & 3))];
#pragma unroll
            for (int o = 16; o; o >>= 1) s += __shfl_xor_sync(0xffffffffu, s, o);
            if (lane == 0) red[warp][idx] = s;
            idx++;
        }
    }
    __syncthreads();
    if (threadIdx.x < NRED) {
        float s = 0.f;
#pragma unroll
        for (int w = 0; w < 8; w++) s += red[w][threadIdx.x];
        g_part[blockIdx.x][threadIdx.x] = s;
    }
}

// =========================================================================
// K2: finalize BN fold (proven)
// =========================================================================
__global__ void k_finalize(const float* __restrict__ conv_w,
                           const float* __restrict__ bn_gamma,
                           const float* __restrict__ bn_beta)
{
    __shared__ float S[NRED];
    int t = threadIdx.x;
    if (t < NRED) {
        float s = 0.f;
        for (int bl = 0; bl < NBLK_MOM; bl++) s += g_part[bl][t];
        S[t] = s * (1.f / (12.f * (float)BATCH));
    }
    __syncthreads();
    if (t < NCH) {
        float w[16];
#pragma unroll
        for (int i = 0; i < 16; i++) w[i] = conv_w[t * 16 + i];
        float mraw = 0.f;
#pragma unroll
        for (int i = 0; i < 16; i++) mraw += w[i] * S[i];
        float q = 0.f;
        int idx = 16;
#pragma unroll
        for (int k = 0; k < 16; k++)
#pragma unroll
            for (int l = k; l < 16; l++) {
                float coef = (k == l) ? (w[k] * w[l]) : (2.f * w[k] * w[l]);
                q += coef * S[idx];
                idx++;
            }
        float var = q - mraw * mraw;
        float a = bn_gamma[t] * rsqrtf(var + EPSV);
#pragma unroll
        for (int i = 0; i < 16; i++) g_wscaled[t * 16 + i] = a * w[i];
        g_shift[t] = bn_beta[t] - a * mraw;
    }
}

// =========================================================================
// K_prep: W1 -> [k'][n] fp16 (hi only).  kp = p*256+c, f = c*12+p.
// =========================================================================
__global__ void k_prep(const float* __restrict__ pw1, const float* __restrict__ vw1)
{
    int kp = blockIdx.x;
    int n  = threadIdx.x;
    int p = kp >> 8, c = kp & 255;
    int f = c * 12 + p;
    float v = (n < 64) ? pw1[(size_t)f * 64 + n] : vw1[(size_t)f * 64 + (n - 64)];
    g_w1hi[(size_t)kp * 128 + n] = __float2half_rn(v);
}

// =========================================================================
// K4: occupancy-optimized fused kernel.
// CTA = 64 boards x 128 outs, 8 warps = 4 m-slices x 2 n-halves.
// Warp tile m16 x n64 -> 32 accumulators -> <=85 regs -> 3 CTAs/SM.
// Per iter (K=64): conv 8 HMMA (dup per n-half) -> fc1 32 HMMA.
// Smem: B ring 3x16384 @0 | Wc hi @49152 | shift @57344  (58368 total)
//       epilogue reuse: h1 [64][129] f32 @0, h2 [64][65] f32 @33152
// =========================================================================
#define NITER    48
#define OFF_B    0
#define OFF_WC   49152
#define OFF_SH   57344
#define SMEM_DYN 58368

__global__ __launch_bounds__(256, 3) void k_fused(
    const float* __restrict__ x,
    const float* __restrict__ pb1, const float* __restrict__ vb1,
    const float* __restrict__ pw2, const float* __restrict__ pb2,
    const float* __restrict__ pw3, const float* __restrict__ pb3,
    const float* __restrict__ vw2, const float* __restrict__ vb2,
    const float* __restrict__ vw3, const float* __restrict__ vb3,
    float* __restrict__ out)
{
    extern __shared__ char dyn_pool[];
    __shared__ float biasS[128];

    char* poolA = dyn_pool;
    const uint32_t pool_u = smem_u32(poolA);

    const int tid  = threadIdx.x;
    const int wid  = tid >> 5;
    const int lane = tid & 31;
    const int m0   = blockIdx.x * 64;
    const int wm   = wid & 3;      // m-slice 0..3
    const int wn   = wid >> 2;     // n-half 0..1

    float* shiftS = (float*)(poolA + OFF_SH);

    // ---- one-time smem fills ----
    if (tid < 64)       biasS[tid] = pb1[tid];
    else if (tid < 128) biasS[tid] = vb1[tid - 64];
    {   // folded conv weights -> Wc[k][c] fp16 (hi), swizzled rows of 512B
#pragma unroll
        for (int i = 0; i < 16; i++) {
            int idx = tid + i * 256;
            int k = idx >> 8, c = idx & 255;
            float v = g_wscaled[c * 16 + k];
            uint32_t o = (uint32_t)k * 512 + ((((uint32_t)(c >> 3)) ^ (k & 7)) << 4) + (c & 7) * 2;
            *(__half*)(poolA + OFF_WC + o) = __float2half_rn(v);
        }
    }
    shiftS[tid] = g_shift[tid];

    // ---- fc1 B cp.async lanes ----
    const int brow = tid >> 2;
    const int bq   = (tid & 3) * 4;
    const __half* gB = g_w1hi + (size_t)brow * 128 + bq * 8;
    uint32_t oBs[4];
#pragma unroll
    for (int j = 0; j < 4; j++)
        oBs[j] = (uint32_t)brow * 256 + ((((uint32_t)(bq + j)) ^ (brow & 7)) << 4);

    // ---- prologue B(0), B(1) ----
#pragma unroll
    for (int pc = 0; pc < 2; pc++) {
        const uint32_t sb = pool_u + OFF_B + pc * 16384;
        const size_t kofs = (size_t)pc * 64 * 128;
#pragma unroll
        for (int j = 0; j < 4; j++)
            CP_ASYNC16(sb + oBs[j], gB + kofs + j * 8);
        CP_COMMIT();
    }

    // ---- lane constants ----
    const int g    = lane >> 2;
    const int t2   = (lane & 3) * 2;
    const int b_kl = ((lane >> 3) & 1) * 8 + (lane & 7);
    const int b_ng = (lane >> 4);
    const uint32_t key = (uint32_t)(b_kl & 7);
    const int xo0 = ((t2 >> 2) * 7 + (t2 & 3));
    const int xo1 = (((t2 + 8) >> 2) * 7 + ((t2 + 8) & 3));

    // D accumulators: m16 x n64 per warp = 8 n8-tiles
    float d[8][4];
#pragma unroll
    for (int nt = 0; nt < 8; nt++)
#pragma unroll
        for (int q = 0; q < 4; q++) d[nt][q] = 0.f;

    __syncthreads();   // Wc / shift visible

    // x-fragment registers (fp16 hi only)
    uint32_t xhi[4];
    {
        const float* xb = x + (size_t)(m0 + wm * 16) * 42;
        xhi[0] = f2h2(xb[(size_t)g * 42 + xo0],       xb[(size_t)g * 42 + xo0 + 1]);
        xhi[1] = f2h2(xb[(size_t)(g + 8) * 42 + xo0], xb[(size_t)(g + 8) * 42 + xo0 + 1]);
        xhi[2] = f2h2(xb[(size_t)g * 42 + xo1],       xb[(size_t)g * 42 + xo1 + 1]);
        xhi[3] = f2h2(xb[(size_t)(g + 8) * 42 + xo1], xb[(size_t)(g + 8) * 42 + xo1 + 1]);
    }

    // ================= main loop =================
#pragma unroll 1
    for (int it = 0; it < NITER; it++) {
        CP_WAIT1();
        __syncthreads();   // B[it%3] arrived & visible

        if (it + 2 < NITER) {
            const uint32_t sb = pool_u + OFF_B + ((it + 2) % 3) * 16384;
            const size_t kofs = (size_t)(it + 2) * 64 * 128;
#pragma unroll
            for (int j = 0; j < 4; j++)
                CP_ASYNC16(sb + oBs[j], gB + kofs + j * 8);
        }
        CP_COMMIT();

        if (it > 0 && (it & 3) == 0) {
            const int p = it >> 2;
            const float* xb = x + (size_t)(m0 + wm * 16) * 42 + (p >> 2) * 7 + (p & 3);
            xhi[0] = f2h2(xb[(size_t)g * 42 + xo0],       xb[(size_t)g * 42 + xo0 + 1]);
            xhi[1] = f2h2(xb[(size_t)(g + 8) * 42 + xo0], xb[(size_t)(g + 8) * 42 + xo0 + 1]);
            xhi[2] = f2h2(xb[(size_t)g * 42 + xo1],       xb[(size_t)g * 42 + xo1 + 1]);
            xhi[3] = f2h2(xb[(size_t)(g + 8) * 42 + xo1], xb[(size_t)(g + 8) * 42 + xo1 + 1]);
        }

        const uint32_t sbB = pool_u + OFF_B + (it % 3) * 16384;

#pragma unroll
        for (int gg = 0; gg < 2; gg++) {
            const int grp = (it & 3) * 2 + gg;
            const int bg  = grp * 4;

            // ---- conv: 2 batched W loads, 4 independent MMAs ----
            uint32_t w0[4], w1[4];
            {
                uint32_t wo0 = (uint32_t)b_kl * 512 + ((((uint32_t)(bg + b_ng)) ^ key) << 4);
                uint32_t wo1 = (uint32_t)b_kl * 512 + ((((uint32_t)(bg + 2 + b_ng)) ^ key) << 4);
                ldsm_x4t(w0, pool_u + OFF_WC + wo0);
                ldsm_x4t(w1, pool_u + OFF_WC + wo1);
            }
            float cd[4][4];
#pragma unroll
            for (int nt = 0; nt < 4; nt++)
#pragma unroll
                for (int q = 0; q < 4; q++) cd[nt][q] = 0.f;
            mma16816(cd[0][0], cd[0][1], cd[0][2], cd[0][3],
                     xhi[0], xhi[1], xhi[2], xhi[3], w0[0], w0[1]);
            mma16816(cd[1][0], cd[1][1], cd[1][2], cd[1][3],
                     xhi[0], xhi[1], xhi[2], xhi[3], w0[2], w0[3]);
            mma16816(cd[2][0], cd[2][1], cd[2][2], cd[2][3],
                     xhi[0], xhi[1], xhi[2], xhi[3], w1[0], w1[1]);
            mma16816(cd[3][0], cd[3][1], cd[3][2], cd[3][3],
                     xhi[0], xhi[1], xhi[2], xhi[3], w1[2], w1[3]);

            // ---- pack: shift + ReLU + fp16 -> 2 A-fragments ----
            uint32_t afr[2][4];
#pragma unroll
            for (int pr = 0; pr < 2; pr++) {
                const float* t0 = cd[pr * 2];
                const float* t1 = cd[pr * 2 + 1];
                float2 s0 = *(const float2*)&shiftS[grp * 32 + pr * 16 + t2];
                float2 s1 = *(const float2*)&shiftS[grp * 32 + pr * 16 + 8 + t2];
                afr[pr][0] = f2h2(fmaxf(t0[0] + s0.x, 0.f), fmaxf(t0[1] + s0.y, 0.f));
                afr[pr][1] = f2h2(fmaxf(t0[2] + s0.x, 0.f), fmaxf(t0[3] + s0.y, 0.f));
                afr[pr][2] = f2h2(fmaxf(t1[0] + s1.x, 0.f), fmaxf(t1[1] + s1.y, 0.f));
                afr[pr][3] = f2h2(fmaxf(t1[2] + s1.x, 0.f), fmaxf(t1[3] + s1.y, 0.f));
            }

            // ---- fc1: 2 k16 chunks; warp covers n-half wn (8 n8-tiles) ----
#pragma unroll
            for (int pr = 0; pr < 2; pr++) {
                const uint32_t* af = afr[pr];
                const uint32_t kbase = sbB + (uint32_t)((gg * 2 + pr) * 16 + b_kl) * 256;
#pragma unroll
                for (int h = 0; h < 2; h++) {
                    uint32_t bA[4], bB[4];
                    uint32_t offA = ((((uint32_t)(wn * 8 + (h * 2 + 0) * 2 + b_ng)) ^ key) << 4);
                    uint32_t offB = ((((uint32_t)(wn * 8 + (h * 2 + 1) * 2 + b_ng)) ^ key) << 4);
                    ldsm_x4t(bA, kbase + offA);
                    ldsm_x4t(bB, kbase + offB);
                    const int n0 = h * 4;
                    mma16816(d[n0][0], d[n0][1], d[n0][2], d[n0][3],
                             af[0], af[1], af[2], af[3], bA[0], bA[1]);
                    mma16816(d[n0 + 1][0], d[n0 + 1][1], d[n0 + 1][2], d[n0 + 1][3],
                             af[0], af[1], af[2], af[3], bA[2], bA[3]);
                    mma16816(d[n0 + 2][0], d[n0 + 2][1], d[n0 + 2][2], d[n0 + 2][3],
                             af[0], af[1], af[2], af[3], bB[0], bB[1]);
                    mma16816(d[n0 + 3][0], d[n0 + 3][1], d[n0 + 3][2], d[n0 + 3][3],
                             af[0], af[1], af[2], af[3], bB[2], bB[3]);
                }
            }
        }
    }

    CP_WAIT0();
    __syncthreads();

    // ---------------- epilogue ----------------
    float* h1 = (float*)poolA;                // [64][129]
    float* h2 = (float*)(poolA + 33152);      // [64][65]

    {
        const int m = wm * 16 + g;
#pragma unroll
        for (int nt = 0; nt < 8; nt++) {
            int n = wn * 64 + nt * 8 + t2;
            h1[m * 129 + n]           = fmaxf(d[nt][0] + biasS[n], 0.f);
            h1[m * 129 + n + 1]       = fmaxf(d[nt][1] + biasS[n + 1], 0.f);
            h1[(m + 8) * 129 + n]     = fmaxf(d[nt][2] + biasS[n], 0.f);
            h1[(m + 8) * 129 + n + 1] = fmaxf(d[nt][3] + biasS[n + 1], 0.f);
        }
    }
    __syncthreads();

    // layer2: 64 boards x 64 outs (32 policy | 32 value)
#pragma unroll 1
    for (int it = 0; it < 16; it++) {
        int idx = it * 256 + tid;
        int bd = idx >> 6, o = idx & 63;
        int oo = o & 31;
        const float* h1b  = h1 + bd * 129 + ((o < 32) ? 0 : 64);
        const float* wmat = (o < 32) ? pw2 : vw2;
        float s = (o < 32) ? pb2[oo] : vb2[oo];
#pragma unroll 8
        for (int k = 0; k < 64; k++) s += h1b[k] * wmat[k * 32 + oo];
        h2[bd * 65 + o] = fmaxf(s, 0.f);
    }
    __syncthreads();

    // layer3 + softmax / tanh
    if (tid < 64) {
        int gb = m0 + tid;
        const float* hp = h2 + tid * 65;
        float lg[7];
#pragma unroll
        for (int j = 0; j < 7; j++) {
            float s = pb3[j];
#pragma unroll
            for (int k = 0; k < 32; k++) s += hp[k] * pw3[k * 7 + j];
            lg[j] = s;
        }
        float mx = lg[0];
#pragma unroll
        for (int j = 1; j < 7; j++) mx = fmaxf(mx, lg[j]);
        float se = 0.f;
#pragma unroll
        for (int j = 0; j < 7; j++) { lg[j] = expf(lg[j] - mx); se += lg[j]; }
        float inv = 1.f / se;
#pragma unroll
        for (int j = 0; j < 7; j++) out[(size_t)gb * 7 + j] = lg[j] * inv;

        float v = vb3[0];
#pragma unroll
        for (int k = 0; k < 32; k++) v += hp[32 + k] * vw3[k];
        out[(size_t)BATCH * 7 + gb] = tanhf(v);
    }
}

// =========================================================================
extern "C" void kernel_launch(void* const* d_in, const int* in_sizes, int n_in,
                              void* d_out, int out_size)
{
    const float* x        = (const float*)d_in[0];
    const float* conv_w   = (const float*)d_in[1];
    /* conv_b cancels through batch-norm */
    const float* bn_gamma = (const float*)d_in[3];
    const float* bn_beta  = (const float*)d_in[4];
    const float* pw1 = (const float*)d_in[5];
    const float* pb1 = (const float*)d_in[6];
    const float* pw2 = (const float*)d_in[7];
    const float* pb2 = (const float*)d_in[8];
    const float* pw3 = (const float*)d_in[9];
    const float* pb3 = (const float*)d_in[10];
    const float* vw1 = (const float*)d_in[11];
    const float* vb1 = (const float*)d_in[12];
    const float* vw2 = (const float*)d_in[13];
    const float* vb2 = (const float*)d_in[14];
    const float* vw3 = (const float*)d_in[15];
    const float* vb3 = (const float*)d_in[16];
    float* out = (float*)d_out;

    cudaFuncSetAttribute(k_fused, cudaFuncAttributeMaxDynamicSharedMemorySize, SMEM_DYN);

    k_moments<<<NBLK_MOM, 256>>>(x);
    k_finalize<<<1, 256>>>(conv_w, bn_gamma, bn_beta);
    k_prep<<<FLAT, 128>>>(pw1, vw1);
    k_fused<<<BATCH / 64, 256, SMEM_DYN>>>(x, pb1, vb1, pw2, pb2, pw3, pb3,
                                           vw2, vb2, vw3, vb3, out);
}

// round 11
// speedup vs baseline: 1.1385x; 1.1385x over previous
#include <cuda_runtime.h>
#include <cuda_fp16.h>
#include <cstdint>

#define BATCH 32768
#define NCH   256
#define FLAT  3072
#define NRED  152
#define NBLK_MOM 128
#define EPSV  1e-5f

// ---------------- device scratch ----------------
__device__ float g_part[NBLK_MOM][NRED];
__device__ float g_wscaled[NCH * 16];
__device__ float g_shift[NCH];
// fc1 weights fp16, TRANSPOSED layout [n][k'], k' = p*256 + c
__device__ __half g_w1t[128 * FLAT];

// ======================= PTX helpers ==================
__device__ __forceinline__ uint32_t smem_u32(const void* p) {
    uint32_t a;
    asm("{ .reg .u64 t; cvta.to.shared.u64 t, %1; cvt.u32.u64 %0, t; }"
        : "=r"(a) : "l"(p));
    return a;
}
#define CP_ASYNC16(dst, src) \
    asm volatile("cp.async.cg.shared.global [%0], [%1], 16;" \
        :: "r"(dst), "l"(src) : "memory")
#define CP_COMMIT() asm volatile("cp.async.commit_group;" ::: "memory")
#define CP_WAIT1()  asm volatile("cp.async.wait_group 1;" ::: "memory")
#define CP_WAIT0()  asm volatile("cp.async.wait_group 0;" ::: "memory")

// NON-trans ldmatrix (fewer L1 wavefronts than .trans)
__device__ __forceinline__ void ldsm_x4(uint32_t r[4], uint32_t addr) {
    asm volatile("ldmatrix.sync.aligned.m8n8.x4.shared.b16 {%0,%1,%2,%3}, [%4];"
        : "=r"(r[0]), "=r"(r[1]), "=r"(r[2]), "=r"(r[3]) : "r"(addr));
}
__device__ __forceinline__ void mma16816(float& d0, float& d1, float& d2, float& d3,
                                         uint32_t a0, uint32_t a1, uint32_t a2, uint32_t a3,
                                         uint32_t b0, uint32_t b1) {
    asm volatile(
        "mma.sync.aligned.m16n8k16.row.col.f32.f16.f16.f32 "
        "{%0,%1,%2,%3}, {%4,%5,%6,%7}, {%8,%9}, {%0,%1,%2,%3};"
        : "+f"(d0), "+f"(d1), "+f"(d2), "+f"(d3)
        : "r"(a0), "r"(a1), "r"(a2), "r"(a3), "r"(b0), "r"(b1));
}
__device__ __forceinline__ uint32_t f2h2(float a, float b) {
    __half2 h = __floats2half2_rn(a, b);
    return *reinterpret_cast<uint32_t*>(&h);
}

// =========================================================================
// K1: patch moments (proven)
// =========================================================================
__global__ void k_moments(const float* __restrict__ x)
{
    int b = blockIdx.x * 256 + threadIdx.x;
    const float* xb = x + b * 42;
    float xv[42];
#pragma unroll
    for (int i = 0; i < 42; i++) xv[i] = xb[i];

    __shared__ float red[8][NRED];
    int lane = threadIdx.x & 31;
    int warp = threadIdx.x >> 5;

    int idx = 0;
#pragma unroll
    for (int k = 0; k < 16; k++) {
        float s = 0.f;
#pragma unroll
        for (int r = 0; r < 3; r++)
#pragma unroll
            for (int c = 0; c < 4; c++)
                s += xv[(r + (k >> 2)) * 7 + (c + (k & 3))];
#pragma unroll
        for (int o = 16; o; o >>= 1) s += __shfl_xor_sync(0xffffffffu, s, o);
        if (lane == 0) red[warp][idx] = s;
        idx++;
    }
#pragma unroll
    for (int k = 0; k < 16; k++) {
#pragma unroll
        for (int l = k; l < 16; l++) {
            float s = 0.f;
#pragma unroll
            for (int r = 0; r < 3; r++)
#pragma unroll
                for (int c = 0; c < 4; c++)
                    s += xv[(r + (k >> 2)) * 7 + (c + (k & 3))] *
                         xv[(r + (l >> 2)) * 7 + (c + (l & 3))];
#pragma unroll
            for (int o = 16; o; o >>= 1) s += __shfl_xor_sync(0xffffffffu, s, o);
            if (lane == 0) red[warp][idx] = s;
            idx++;
        }
    }
    __syncthreads();
    if (threadIdx.x < NRED) {
        float s = 0.f;
#pragma unroll
        for (int w = 0; w < 8; w++) s += red[w][threadIdx.x];
        g_part[blockIdx.x][threadIdx.x] = s;
    }
}

// =========================================================================
// K2: finalize BN fold (proven)
// =========================================================================
__global__ void k_finalize(const float* __restrict__ conv_w,
                           const float* __restrict__ bn_gamma,
                           const float* __restrict__ bn_beta)
{
    __shared__ float S[NRED];
    int t = threadIdx.x;
    if (t < NRED) {
        float s = 0.f;
        for (int bl = 0; bl < NBLK_MOM; bl++) s += g_part[bl][t];
        S[t] = s * (1.f / (12.f * (float)BATCH));
    }
    __syncthreads();
    if (t < NCH) {
        float w[16];
#pragma unroll
        for (int i = 0; i < 16; i++) w[i] = conv_w[t * 16 + i];
        float mraw = 0.f;
#pragma unroll
        for (int i = 0; i < 16; i++) mraw += w[i] * S[i];
        float q = 0.f;
        int idx = 16;
#pragma unroll
        for (int k = 0; k < 16; k++)
#pragma unroll
            for (int l = k; l < 16; l++) {
                float coef = (k == l) ? (w[k] * w[l]) : (2.f * w[k] * w[l]);
                q += coef * S[idx];
                idx++;
            }
        float var = q - mraw * mraw;
        float a = bn_gamma[t] * rsqrtf(var + EPSV);
#pragma unroll
        for (int i = 0; i < 16; i++) g_wscaled[t * 16 + i] = a * w[i];
        g_shift[t] = bn_beta[t] - a * mraw;
    }
}

// =========================================================================
// K_prep: W1 -> TRANSPOSED [n][k'] fp16.  kp = p*256+c, f = c*12+p.
// Coalesced: one block per n, threads stride kp.
// =========================================================================
__global__ void k_prep(const float* __restrict__ pw1, const float* __restrict__ vw1)
{
    int n = blockIdx.x;   // 0..127
    for (int kp = threadIdx.x; kp < FLAT; kp += 256) {
        int p = kp >> 8, c = kp & 255;
        int f = c * 12 + p;
        float v = (n < 64) ? pw1[(size_t)f * 64 + n] : vw1[(size_t)f * 64 + (n - 64)];
        g_w1t[(size_t)n * FLAT + kp] = __float2half_rn(v);
    }
}

// =========================================================================
// K4: fused kernel, L1-optimized: non-trans ldmatrix everywhere,
// warp tile m32 x n64 (8 warps = 4 m-slices x 2 n-halves, CTA 128 boards).
// Per iter (K=64) per warp: conv 4 LDSM + 16 HMMA; fc1 16 LDSM + 64 HMMA.
// Smem: B ring 3 x 16384 @0 ([n=128 rows][128B k], 8-chunk XOR swizzle)
//       Wc [c=256 rows][48B: 32B k + 16B pad] @49152 (12288)
//       shift @61440 (1024)
// Epilogue reuse: h1 [128][129] f32 @0, h2 [128][65] @66560; SMEM_DYN 99840.
// =========================================================================
#define NITER    48
#define OFF_B    0
#define OFF_WC   49152
#define OFF_SH   61440
#define SMEM_DYN 99840

__global__ __launch_bounds__(256, 2) void k_fused(
    const float* __restrict__ x,
    const float* __restrict__ pb1, const float* __restrict__ vb1,
    const float* __restrict__ pw2, const float* __restrict__ pb2,
    const float* __restrict__ pw3, const float* __restrict__ pb3,
    const float* __restrict__ vw2, const float* __restrict__ vb2,
    const float* __restrict__ vw3, const float* __restrict__ vb3,
    float* __restrict__ out)
{
    extern __shared__ char dyn_pool[];
    __shared__ float biasS[128];

    char* poolA = dyn_pool;
    const uint32_t pool_u = smem_u32(poolA);

    const int tid  = threadIdx.x;
    const int wid  = tid >> 5;
    const int lane = tid & 31;
    const int m0   = blockIdx.x * 128;
    const int wm   = wid & 3;      // m-slice (32 boards)
    const int wn   = wid >> 2;     // n-half (64 outs)

    float* shiftS = (float*)(poolA + OFF_SH);

    // ---- one-time smem fills ----
    if (tid < 64)       biasS[tid] = pb1[tid];
    else if (tid < 128) biasS[tid] = vb1[tid - 64];
    {   // folded conv weights -> Wc[c][k] fp16, 48B row stride (pad kills conflicts)
#pragma unroll
        for (int i = 0; i < 16; i++) {
            int idx = tid + i * 256;
            int k = idx >> 8, c = idx & 255;
            float v = g_wscaled[c * 16 + k];
            uint32_t o = (uint32_t)c * 48 + (uint32_t)(k >> 3) * 16 + (uint32_t)(k & 7) * 2;
            *(__half*)(poolA + OFF_WC + o) = __float2half_rn(v);
        }
    }
    shiftS[tid] = g_shift[tid];

    // ---- fc1 B cp.async lanes: [n][k] tile, n=tid>>1 row, 4x16B per thread ----
    const int bn   = tid >> 1;              // 0..127 (n row)
    const int bh   = (tid & 1) * 4;         // chunk base 0 or 4
    const __half* gB = g_w1t + (size_t)bn * FLAT + bh * 8;
    uint32_t oBs[4];
#pragma unroll
    for (int j = 0; j < 4; j++)
        oBs[j] = (uint32_t)bn * 128 + ((((uint32_t)(bh + j)) ^ (bn & 7)) << 4);

    // ---- prologue B(0), B(1) ----
#pragma unroll
    for (int pc = 0; pc < 2; pc++) {
        const uint32_t sb = pool_u + OFF_B + pc * 16384;
        const size_t kofs = (size_t)pc * 64;
#pragma unroll
        for (int j = 0; j < 4; j++)
            CP_ASYNC16(sb + oBs[j], gB + kofs + j * 8);
        CP_COMMIT();
    }

    // ---- lane constants ----
    const int g     = lane >> 2;                       // frag row
    const int t2    = (lane & 3) * 2;                  // frag col pair
    const int lrow  = (lane & 7) + ((lane >> 4) & 1) * 8;  // ldsm row-in-16
    const int khalf = (lane >> 3) & 1;                 // ldsm k-half select
    const int xo0 = ((t2 >> 2) * 7 + (t2 & 3));
    const int xo1 = (((t2 + 8) >> 2) * 7 + ((t2 + 8) & 3));

    // fc1 B ldsm bases per n16-group (np = 0..3 within this warp's n64)
    uint32_t fbase[4], fkey[4];
#pragma unroll
    for (int np = 0; np < 4; np++) {
        uint32_t nrow = (uint32_t)(wn * 64 + np * 16 + lrow);
        fbase[np] = nrow * 128;
        fkey[np]  = nrow & 7;
    }
    // conv W ldsm lane offset
    const uint32_t wlane = (uint32_t)lrow * 48 + (uint32_t)khalf * 16;

    // D accumulators: m32 x n64 per warp = 2 m-halves x 8 n8-tiles
    float d[2][8][4];
#pragma unroll
    for (int mh = 0; mh < 2; mh++)
#pragma unroll
        for (int nt = 0; nt < 8; nt++)
#pragma unroll
            for (int q = 0; q < 4; q++) d[mh][nt][q] = 0.f;

    __syncthreads();   // Wc / shift visible

    // x fragments for both m-halves (fp16 hi only)
    uint32_t xhi[2][4];
#pragma unroll
    for (int mh = 0; mh < 2; mh++) {
        const float* xb = x + (size_t)(m0 + wm * 32 + mh * 16) * 42;
        xhi[mh][0] = f2h2(xb[(size_t)g * 42 + xo0],       xb[(size_t)g * 42 + xo0 + 1]);
        xhi[mh][1] = f2h2(xb[(size_t)(g + 8) * 42 + xo0], xb[(size_t)(g + 8) * 42 + xo0 + 1]);
        xhi[mh][2] = f2h2(xb[(size_t)g * 42 + xo1],       xb[(size_t)g * 42 + xo1 + 1]);
        xhi[mh][3] = f2h2(xb[(size_t)(g + 8) * 42 + xo1], xb[(size_t)(g + 8) * 42 + xo1 + 1]);
    }

    // ================= main loop =================
#pragma unroll 1
    for (int it = 0; it < NITER; it++) {
        CP_WAIT1();
        __syncthreads();   // B[it%3] arrived & visible

        if (it + 2 < NITER) {
            const uint32_t sb = pool_u + OFF_B + ((it + 2) % 3) * 16384;
            const size_t kofs = (size_t)(it + 2) * 64;
#pragma unroll
            for (int j = 0; j < 4; j++)
                CP_ASYNC16(sb + oBs[j], gB + kofs + j * 8);
        }
        CP_COMMIT();

        if (it > 0 && (it & 3) == 0) {
            const int p = it >> 2;
            const int po = (p >> 2) * 7 + (p & 3);
#pragma unroll
            for (int mh = 0; mh < 2; mh++) {
                const float* xb = x + (size_t)(m0 + wm * 32 + mh * 16) * 42 + po;
                xhi[mh][0] = f2h2(xb[(size_t)g * 42 + xo0],       xb[(size_t)g * 42 + xo0 + 1]);
                xhi[mh][1] = f2h2(xb[(size_t)(g + 8) * 42 + xo0], xb[(size_t)(g + 8) * 42 + xo0 + 1]);
                xhi[mh][2] = f2h2(xb[(size_t)g * 42 + xo1],       xb[(size_t)g * 42 + xo1 + 1]);
                xhi[mh][3] = f2h2(xb[(size_t)(g + 8) * 42 + xo1], xb[(size_t)(g + 8) * 42 + xo1 + 1]);
            }
        }

        const uint32_t sbB = pool_u + OFF_B + (it % 3) * 16384;

#pragma unroll
        for (int gg = 0; gg < 2; gg++) {
            const int grp = (it & 3) * 2 + gg;

            // ---- conv W loads (non-trans, shared across m-halves) ----
            uint32_t w0[4], w1[4];
            {
                uint32_t cb = pool_u + OFF_WC + (uint32_t)(grp * 32) * 48 + wlane;
                ldsm_x4(w0, cb);
                ldsm_x4(w1, cb + 16 * 48);
            }

            // ---- conv per m-half -> A fragments afr[mh][pr] ----
            uint32_t afr[2][2][4];
#pragma unroll
            for (int mh = 0; mh < 2; mh++) {
                float cd[4][4];
#pragma unroll
                for (int nt = 0; nt < 4; nt++)
#pragma unroll
                    for (int q = 0; q < 4; q++) cd[nt][q] = 0.f;
                mma16816(cd[0][0], cd[0][1], cd[0][2], cd[0][3],
                         xhi[mh][0], xhi[mh][1], xhi[mh][2], xhi[mh][3], w0[0], w0[1]);
                mma16816(cd[1][0], cd[1][1], cd[1][2], cd[1][3],
                         xhi[mh][0], xhi[mh][1], xhi[mh][2], xhi[mh][3], w0[2], w0[3]);
                mma16816(cd[2][0], cd[2][1], cd[2][2], cd[2][3],
                         xhi[mh][0], xhi[mh][1], xhi[mh][2], xhi[mh][3], w1[0], w1[1]);
                mma16816(cd[3][0], cd[3][1], cd[3][2], cd[3][3],
                         xhi[mh][0], xhi[mh][1], xhi[mh][2], xhi[mh][3], w1[2], w1[3]);
#pragma unroll
                for (int pr = 0; pr < 2; pr++) {
                    const float* t0 = cd[pr * 2];
                    const float* t1 = cd[pr * 2 + 1];
                    float2 s0 = *(const float2*)&shiftS[grp * 32 + pr * 16 + t2];
                    float2 s1 = *(const float2*)&shiftS[grp * 32 + pr * 16 + 8 + t2];
                    afr[mh][pr][0] = f2h2(fmaxf(t0[0] + s0.x, 0.f), fmaxf(t0[1] + s0.y, 0.f));
                    afr[mh][pr][1] = f2h2(fmaxf(t0[2] + s0.x, 0.f), fmaxf(t0[3] + s0.y, 0.f));
                    afr[mh][pr][2] = f2h2(fmaxf(t1[0] + s1.x, 0.f), fmaxf(t1[1] + s1.y, 0.f));
                    afr[mh][pr][3] = f2h2(fmaxf(t1[2] + s1.x, 0.f), fmaxf(t1[3] + s1.y, 0.f));
                }
            }

            // ---- fc1: 2 k16 chunks; 4 non-trans LDSM each feed 4 HMMA ----
#pragma unroll
            for (int pr = 0; pr < 2; pr++) {
                const uint32_t kk = (uint32_t)((gg * 2 + pr) * 2 + khalf);
#pragma unroll
                for (int np = 0; np < 4; np++) {
                    uint32_t b4[4];
                    ldsm_x4(b4, sbB + fbase[np] + ((kk ^ fkey[np]) << 4));
#pragma unroll
                    for (int mh = 0; mh < 2; mh++) {
                        float* d0 = d[mh][np * 2];
                        float* d1 = d[mh][np * 2 + 1];
                        mma16816(d0[0], d0[1], d0[2], d0[3],
                                 afr[mh][pr][0], afr[mh][pr][1],
                                 afr[mh][pr][2], afr[mh][pr][3], b4[0], b4[1]);
                        mma16816(d1[0], d1[1], d1[2], d1[3],
                                 afr[mh][pr][0], afr[mh][pr][1],
                                 afr[mh][pr][2], afr[mh][pr][3], b4[2], b4[3]);
                    }
                }
            }
        }
    }

    CP_WAIT0();
    __syncthreads();

    // ---------------- epilogue ----------------
    float* h1 = (float*)poolA;              // [128][129]
    float* h2 = (float*)(poolA + 66560);    // [128][65]

    {
#pragma unroll
        for (int mh = 0; mh < 2; mh++) {
            const int m = wm * 32 + mh * 16 + g;
#pragma unroll
            for (int nt = 0; nt < 8; nt++) {
                int n = wn * 64 + nt * 8 + t2;
                h1[m * 129 + n]           = fmaxf(d[mh][nt][0] + biasS[n], 0.f);
                h1[m * 129 + n + 1]       = fmaxf(d[mh][nt][1] + biasS[n + 1], 0.f);
                h1[(m + 8) * 129 + n]     = fmaxf(d[mh][nt][2] + biasS[n], 0.f);
                h1[(m + 8) * 129 + n + 1] = fmaxf(d[mh][nt][3] + biasS[n + 1], 0.f);
            }
        }
    }
    __syncthreads();

    // layer2: 128 boards x 64 outs (32 policy | 32 value)
#pragma unroll 1
    for (int it = 0; it < 32; it++) {
        int idx = it * 256 + tid;
        int bd = idx >> 6, o = idx & 63;
        int oo = o & 31;
        const float* h1b  = h1 + bd * 129 + ((o < 32) ? 0 : 64);
        const float* wmat = (o < 32) ? pw2 : vw2;
        float s = (o < 32) ? pb2[oo] : vb2[oo];
#pragma unroll 8
        for (int k = 0; k < 64; k++) s += h1b[k] * wmat[k * 32 + oo];
        h2[bd * 65 + o] = fmaxf(s, 0.f);
    }
    __syncthreads();

    // layer3 + softmax / tanh
    if (tid < 128) {
        int gb = m0 + tid;
        const float* hp = h2 + tid * 65;
        float lg[7];
#pragma unroll
        for (int j = 0; j < 7; j++) {
            float s = pb3[j];
#pragma unroll
            for (int k = 0; k < 32; k++) s += hp[k] * pw3[k * 7 + j];
            lg[j] = s;
        }
        float mx = lg[0];
#pragma unroll
        for (int j = 1; j < 7; j++) mx = fmaxf(mx, lg[j]);
        float se = 0.f;
#pragma unroll
        for (int j = 0; j < 7; j++) { lg[j] = expf(lg[j] - mx); se += lg[j]; }
        float inv = 1.f / se;
#pragma unroll
        for (int j = 0; j < 7; j++) out[(size_t)gb * 7 + j] = lg[j] * inv;

        float v = vb3[0];
#pragma unroll
        for (int k = 0; k < 32; k++) v += hp[32 + k] * vw3[k];
        out[(size_t)BATCH * 7 + gb] = tanhf(v);
    }
}

// =========================================================================
extern "C" void kernel_launch(void* const* d_in, const int* in_sizes, int n_in,
                              void* d_out, int out_size)
{
    const float* x        = (const float*)d_in[0];
    const float* conv_w   = (const float*)d_in[1];
    /* conv_b cancels through batch-norm */
    const float* bn_gamma = (const float*)d_in[3];
    const float* bn_beta  = (const float*)d_in[4];
    const float* pw1 = (const float*)d_in[5];
    const float* pb1 = (const float*)d_in[6];
    const float* pw2 = (const float*)d_in[7];
    const float* pb2 = (const float*)d_in[8];
    const float* pw3 = (const float*)d_in[9];
    const float* pb3 = (const float*)d_in[10];
    const float* vw1 = (const float*)d_in[11];
    const float* vb1 = (const float*)d_in[12];
    const float* vw2 = (const float*)d_in[13];
    const float* vb2 = (const float*)d_in[14];
    const float* vw3 = (const float*)d_in[15];
    const float* vb3 = (const float*)d_in[16];
    float* out = (float*)d_out;

    cudaFuncSetAttribute(k_fused, cudaFuncAttributeMaxDynamicSharedMemorySize, SMEM_DYN);

    k_moments<<<NBLK_MOM, 256>>>(x);
    k_finalize<<<1, 256>>>(conv_w, bn_gamma, bn_beta);
    k_prep<<<128, 256>>>(pw1, vw1);
    k_fused<<<BATCH / 128, 256, SMEM_DYN>>>(x, pb1, vb1, pw2, pb2, pw3, pb3,
                                            vw2, vb2, vw3, vb3, out);
}

// round 12
// speedup vs baseline: 1.1530x; 1.0127x over previous
#include <cuda_runtime.h>
#include <cuda_fp16.h>
#include <cstdint>

#define BATCH 32768
#define NCH   256
#define FLAT  3072
#define NRED  152
#define NBLK_MOM 128
#define EPSV  1e-5f

// ---------------- device scratch ----------------
__device__ float g_part[NBLK_MOM][NRED];
__device__ float g_wscaled[NCH * 16];
__device__ float g_shift[NCH];
// fc1 weights fp16, TRANSPOSED layout [n][k'], k' = p*256 + c
__device__ __half g_w1t[128 * FLAT];

// ======================= PTX helpers ==================
__device__ __forceinline__ uint32_t smem_u32(const void* p) {
    uint32_t a;
    asm("{ .reg .u64 t; cvta.to.shared.u64 t, %1; cvt.u32.u64 %0, t; }"
        : "=r"(a) : "l"(p));
    return a;
}
#define CP_ASYNC16(dst, src) \
    asm volatile("cp.async.cg.shared.global [%0], [%1], 16;" \
        :: "r"(dst), "l"(src) : "memory")
#define CP_COMMIT() asm volatile("cp.async.commit_group;" ::: "memory")
#define CP_WAIT0()  asm volatile("cp.async.wait_group 0;" ::: "memory")

// NON-trans ldmatrix
__device__ __forceinline__ void ldsm_x4(uint32_t r[4], uint32_t addr) {
    asm volatile("ldmatrix.sync.aligned.m8n8.x4.shared.b16 {%0,%1,%2,%3}, [%4];"
        : "=r"(r[0]), "=r"(r[1]), "=r"(r[2]), "=r"(r[3]) : "r"(addr));
}
__device__ __forceinline__ void mma16816(float& d0, float& d1, float& d2, float& d3,
                                         uint32_t a0, uint32_t a1, uint32_t a2, uint32_t a3,
                                         uint32_t b0, uint32_t b1) {
    asm volatile(
        "mma.sync.aligned.m16n8k16.row.col.f32.f16.f16.f32 "
        "{%0,%1,%2,%3}, {%4,%5,%6,%7}, {%8,%9}, {%0,%1,%2,%3};"
        : "+f"(d0), "+f"(d1), "+f"(d2), "+f"(d3)
        : "r"(a0), "r"(a1), "r"(a2), "r"(a3), "r"(b0), "r"(b1));
}
__device__ __forceinline__ uint32_t f2h2(float a, float b) {
    __half2 h = __floats2half2_rn(a, b);
    return *reinterpret_cast<uint32_t*>(&h);
}

// =========================================================================
// K1: patch moments (proven)
// =========================================================================
__global__ void k_moments(const float* __restrict__ x)
{
    int b = blockIdx.x * 256 + threadIdx.x;
    const float* xb = x + b * 42;
    float xv[42];
#pragma unroll
    for (int i = 0; i < 42; i++) xv[i] = xb[i];

    __shared__ float red[8][NRED];
    int lane = threadIdx.x & 31;
    int warp = threadIdx.x >> 5;

    int idx = 0;
#pragma unroll
    for (int k = 0; k < 16; k++) {
        float s = 0.f;
#pragma unroll
        for (int r = 0; r < 3; r++)
#pragma unroll
            for (int c = 0; c < 4; c++)
                s += xv[(r + (k >> 2)) * 7 + (c + (k & 3))];
#pragma unroll
        for (int o = 16; o; o >>= 1) s += __shfl_xor_sync(0xffffffffu, s, o);
        if (lane == 0) red[warp][idx] = s;
        idx++;
    }
#pragma unroll
    for (int k = 0; k < 16; k++) {
#pragma unroll
        for (int l = k; l < 16; l++) {
            float s = 0.f;
#pragma unroll
            for (int r = 0; r < 3; r++)
#pragma unroll
                for (int c = 0; c < 4; c++)
                    s += xv[(r + (k >> 2)) * 7 + (c + (k & 3))] *
                         xv[(r + (l >> 2)) * 7 + (c + (l & 3))];
#pragma unroll
            for (int o = 16; o; o >>= 1) s += __shfl_xor_sync(0xffffffffu, s, o);
            if (lane == 0) red[warp][idx] = s;
            idx++;
        }
    }
    __syncthreads();
    if (threadIdx.x < NRED) {
        float s = 0.f;
#pragma unroll
        for (int w = 0; w < 8; w++) s += red[w][threadIdx.x];
        g_part[blockIdx.x][threadIdx.x] = s;
    }
}

// =========================================================================
// K2: finalize BN fold (proven)
// =========================================================================
__global__ void k_finalize(const float* __restrict__ conv_w,
                           const float* __restrict__ bn_gamma,
                           const float* __restrict__ bn_beta)
{
    __shared__ float S[NRED];
    int t = threadIdx.x;
    if (t < NRED) {
        float s = 0.f;
        for (int bl = 0; bl < NBLK_MOM; bl++) s += g_part[bl][t];
        S[t] = s * (1.f / (12.f * (float)BATCH));
    }
    __syncthreads();
    if (t < NCH) {
        float w[16];
#pragma unroll
        for (int i = 0; i < 16; i++) w[i] = conv_w[t * 16 + i];
        float mraw = 0.f;
#pragma unroll
        for (int i = 0; i < 16; i++) mraw += w[i] * S[i];
        float q = 0.f;
        int idx = 16;
#pragma unroll
        for (int k = 0; k < 16; k++)
#pragma unroll
            for (int l = k; l < 16; l++) {
                float coef = (k == l) ? (w[k] * w[l]) : (2.f * w[k] * w[l]);
                q += coef * S[idx];
                idx++;
            }
        float var = q - mraw * mraw;
        float a = bn_gamma[t] * rsqrtf(var + EPSV);
#pragma unroll
        for (int i = 0; i < 16; i++) g_wscaled[t * 16 + i] = a * w[i];
        g_shift[t] = bn_beta[t] - a * mraw;
    }
}

// =========================================================================
// K_prep: W1 -> TRANSPOSED [n][k'] fp16.  kp = p*256+c, f = c*12+p.
// =========================================================================
__global__ void k_prep(const float* __restrict__ pw1, const float* __restrict__ vw1)
{
    int n = blockIdx.x;   // 0..127
    for (int kp = threadIdx.x; kp < FLAT; kp += 256) {
        int p = kp >> 8, c = kp & 255;
        int f = c * 12 + p;
        float v = (n < 64) ? pw1[(size_t)f * 64 + n] : vw1[(size_t)f * 64 + (n - 64)];
        g_w1t[(size_t)n * FLAT + kp] = __float2half_rn(v);
    }
}

// =========================================================================
// K4: fused kernel, K=128 per iteration (24 iters), one barrier per iter.
// Warp tile m32 x n64 (8 warps = 4 m-slices x 2 n-halves, CTA 128 boards).
// Per iter per warp: conv 8 LDSM + 32 HMMA; fc1 32 LDSM + 128 HMMA; pack 64 f2h2.
// Smem: B ring 2 x 32768 @0 (each slot = 2 sub-tiles [128 rows][128B])
//       Wc [c][k] 48B rows @65536 (12288) | shift float2 @77824 (1024)
// Epilogue reuse: h1 [128][129] f32 @0, h2 [128][65] @66560; SMEM_DYN 99840.
// =========================================================================
#define NITER    24
#define OFF_B    0
#define OFF_WC   65536
#define OFF_SH   77824
#define SMEM_DYN 99840

__global__ __launch_bounds__(256, 2) void k_fused(
    const float* __restrict__ x,
    const float* __restrict__ pb1, const float* __restrict__ vb1,
    const float* __restrict__ pw2, const float* __restrict__ pb2,
    const float* __restrict__ pw3, const float* __restrict__ pb3,
    const float* __restrict__ vw2, const float* __restrict__ vb2,
    const float* __restrict__ vw3, const float* __restrict__ vb3,
    float* __restrict__ out)
{
    extern __shared__ char dyn_pool[];
    __shared__ float biasS[128];

    char* poolA = dyn_pool;
    const uint32_t pool_u = smem_u32(poolA);

    const int tid  = threadIdx.x;
    const int wid  = tid >> 5;
    const int lane = tid & 31;
    const int m0   = blockIdx.x * 128;
    const int wm   = wid & 3;      // m-slice (32 boards)
    const int wn   = wid >> 2;     // n-half (64 outs)

    float2* shiftS2 = (float2*)(poolA + OFF_SH);   // [128] channel pairs

    // ---- one-time smem fills ----
    if (tid < 64)       biasS[tid] = pb1[tid];
    else if (tid < 128) biasS[tid] = vb1[tid - 64];
    {   // folded conv weights -> Wc[c][k] fp16, 48B row stride
#pragma unroll
        for (int i = 0; i < 16; i++) {
            int idx = tid + i * 256;
            int k = idx >> 8, c = idx & 255;
            float v = g_wscaled[c * 16 + k];
            uint32_t o = (uint32_t)c * 48 + (uint32_t)(k >> 3) * 16 + (uint32_t)(k & 7) * 2;
            *(__half*)(poolA + OFF_WC + o) = __float2half_rn(v);
        }
    }
    if (tid < 128) {   // shift as float2 pairs
        shiftS2[tid] = make_float2(g_shift[tid * 2], g_shift[tid * 2 + 1]);
    }

    // ---- fc1 B cp.async lanes: [n][k] rows of 128B per sub-tile ----
    const int bn = tid >> 1;              // n row 0..127
    const int bh = (tid & 1) * 4;         // chunk base 0 or 4
    const __half* gB = g_w1t + (size_t)bn * FLAT + bh * 8;
    uint32_t oBs[4];
#pragma unroll
    for (int j = 0; j < 4; j++)
        oBs[j] = (uint32_t)bn * 128 + ((((uint32_t)(bh + j)) ^ (bn & 7)) << 4);

    // ---- prologue: B(0) into slot 0 ----
    {
        const uint32_t sb = pool_u + OFF_B;
#pragma unroll
        for (int j = 0; j < 4; j++) {
            CP_ASYNC16(sb + oBs[j], gB + j * 8);                    // k [0,64)
            CP_ASYNC16(sb + 16384 + oBs[j], gB + 64 + j * 8);       // k [64,128)
        }
        CP_COMMIT();
    }

    // ---- lane constants ----
    const int g     = lane >> 2;
    const int t2    = (lane & 3) * 2;
    const int lrow  = (lane & 7) + ((lane >> 4) & 1) * 8;
    const int khalf = (lane >> 3) & 1;
    const int xo0 = ((t2 >> 2) * 7 + (t2 & 3));
    const int xo1 = (((t2 + 8) >> 2) * 7 + ((t2 + 8) & 3));

    uint32_t fbase[4], fkey[4];
#pragma unroll
    for (int np = 0; np < 4; np++) {
        uint32_t nrow = (uint32_t)(wn * 64 + np * 16 + lrow);
        fbase[np] = nrow * 128;
        fkey[np]  = nrow & 7;
    }
    const uint32_t wlane = (uint32_t)lrow * 48 + (uint32_t)khalf * 16;

    // D accumulators: m32 x n64 per warp
    float d[2][8][4];
#pragma unroll
    for (int mh = 0; mh < 2; mh++)
#pragma unroll
        for (int nt = 0; nt < 8; nt++)
#pragma unroll
            for (int q = 0; q < 4; q++) d[mh][nt][q] = 0.f;

    __syncthreads();   // Wc / shift visible

    // x fragments for both m-halves
    uint32_t xhi[2][4];
#pragma unroll
    for (int mh = 0; mh < 2; mh++) {
        const float* xb = x + (size_t)(m0 + wm * 32 + mh * 16) * 42;
        xhi[mh][0] = f2h2(xb[(size_t)g * 42 + xo0],       xb[(size_t)g * 42 + xo0 + 1]);
        xhi[mh][1] = f2h2(xb[(size_t)(g + 8) * 42 + xo0], xb[(size_t)(g + 8) * 42 + xo0 + 1]);
        xhi[mh][2] = f2h2(xb[(size_t)g * 42 + xo1],       xb[(size_t)g * 42 + xo1 + 1]);
        xhi[mh][3] = f2h2(xb[(size_t)(g + 8) * 42 + xo1], xb[(size_t)(g + 8) * 42 + xo1 + 1]);
    }

    // ================= main loop (24 iters of K=128) =================
#pragma unroll 1
    for (int it = 0; it < NITER; it++) {
        CP_WAIT0();        // B(it) complete (issued one full iteration ago)
        __syncthreads();   // visibility + slot (it+1)&1 free to overwrite

        if (it + 1 < NITER) {
            const uint32_t sb = pool_u + OFF_B + ((it + 1) & 1) * 32768;
            const size_t kofs = (size_t)(it + 1) * 128;
#pragma unroll
            for (int j = 0; j < 4; j++) {
                CP_ASYNC16(sb + oBs[j], gB + kofs + j * 8);
                CP_ASYNC16(sb + 16384 + oBs[j], gB + kofs + 64 + j * 8);
            }
            CP_COMMIT();
        }

        // x rebuild every 2 iterations (patch p = it>>1)
        if (it > 0 && (it & 1) == 0) {
            const int p = it >> 1;
            const int po = (p >> 2) * 7 + (p & 3);
#pragma unroll
            for (int mh = 0; mh < 2; mh++) {
                const float* xb = x + (size_t)(m0 + wm * 32 + mh * 16) * 42 + po;
                xhi[mh][0] = f2h2(xb[(size_t)g * 42 + xo0],       xb[(size_t)g * 42 + xo0 + 1]);
                xhi[mh][1] = f2h2(xb[(size_t)(g + 8) * 42 + xo0], xb[(size_t)(g + 8) * 42 + xo0 + 1]);
                xhi[mh][2] = f2h2(xb[(size_t)g * 42 + xo1],       xb[(size_t)g * 42 + xo1 + 1]);
                xhi[mh][3] = f2h2(xb[(size_t)(g + 8) * 42 + xo1], xb[(size_t)(g + 8) * 42 + xo1 + 1]);
            }
        }

        const uint32_t sbB = pool_u + OFF_B + (it & 1) * 32768;

#pragma unroll
        for (int gg = 0; gg < 4; gg++) {
            const int grp  = it * 4 + gg;        // global group 0..95
            const int grp8 = grp & 7;            // channel group

            // shift pairs for this group's 4 n8-tiles (shared across m-halves)
            float2 sv[4];
#pragma unroll
            for (int nt = 0; nt < 4; nt++)
                sv[nt] = shiftS2[grp8 * 16 + nt * 4 + (t2 >> 1)];

            // ---- conv W loads (non-trans) ----
            uint32_t w0[4], w1[4];
            {
                uint32_t cb = pool_u + OFF_WC + (uint32_t)(grp8 * 32) * 48 + wlane;
                ldsm_x4(w0, cb);
                ldsm_x4(w1, cb + 16 * 48);
            }

            // ---- conv per m-half (accumulators INIT to shift) ----
            uint32_t afr[2][2][4];
#pragma unroll
            for (int mh = 0; mh < 2; mh++) {
                float cd[4][4];
#pragma unroll
                for (int nt = 0; nt < 4; nt++) {
                    cd[nt][0] = sv[nt].x; cd[nt][1] = sv[nt].y;
                    cd[nt][2] = sv[nt].x; cd[nt][3] = sv[nt].y;
                }
                mma16816(cd[0][0], cd[0][1], cd[0][2], cd[0][3],
                         xhi[mh][0], xhi[mh][1], xhi[mh][2], xhi[mh][3], w0[0], w0[1]);
                mma16816(cd[1][0], cd[1][1], cd[1][2], cd[1][3],
                         xhi[mh][0], xhi[mh][1], xhi[mh][2], xhi[mh][3], w0[2], w0[3]);
                mma16816(cd[2][0], cd[2][1], cd[2][2], cd[2][3],
                         xhi[mh][0], xhi[mh][1], xhi[mh][2], xhi[mh][3], w1[0], w1[1]);
                mma16816(cd[3][0], cd[3][1], cd[3][2], cd[3][3],
                         xhi[mh][0], xhi[mh][1], xhi[mh][2], xhi[mh][3], w1[2], w1[3]);
#pragma unroll
                for (int pr = 0; pr < 2; pr++) {
                    const float* t0 = cd[pr * 2];
                    const float* t1 = cd[pr * 2 + 1];
                    afr[mh][pr][0] = f2h2(fmaxf(t0[0], 0.f), fmaxf(t0[1], 0.f));
                    afr[mh][pr][1] = f2h2(fmaxf(t0[2], 0.f), fmaxf(t0[3], 0.f));
                    afr[mh][pr][2] = f2h2(fmaxf(t1[0], 0.f), fmaxf(t1[1], 0.f));
                    afr[mh][pr][3] = f2h2(fmaxf(t1[2], 0.f), fmaxf(t1[3], 0.f));
                }
            }

            // ---- fc1: 2 k16 chunks; 4 non-trans LDSM each feed 4 HMMA ----
#pragma unroll
            for (int pr = 0; pr < 2; pr++) {
                const int c16 = gg * 2 + pr;                 // k16 index 0..7
                const uint32_t sub = sbB + (uint32_t)(c16 >> 2) * 16384;
                const uint32_t kk  = (uint32_t)((c16 & 3) * 2 + khalf);
#pragma unroll
                for (int np = 0; np < 4; np++) {
                    uint32_t b4[4];
                    ldsm_x4(b4, sub + fbase[np] + ((kk ^ fkey[np]) << 4));
#pragma unroll
                    for (int mh = 0; mh < 2; mh++) {
                        float* d0 = d[mh][np * 2];
                        float* d1 = d[mh][np * 2 + 1];
                        mma16816(d0[0], d0[1], d0[2], d0[3],
                                 afr[mh][pr][0], afr[mh][pr][1],
                                 afr[mh][pr][2], afr[mh][pr][3], b4[0], b4[1]);
                        mma16816(d1[0], d1[1], d1[2], d1[3],
                                 afr[mh][pr][0], afr[mh][pr][1],
                                 afr[mh][pr][2], afr[mh][pr][3], b4[2], b4[3]);
                    }
                }
            }
        }
    }

    __syncthreads();

    // ---------------- epilogue ----------------
    float* h1 = (float*)poolA;              // [128][129]
    float* h2 = (float*)(poolA + 66560);    // [128][65]

    {
#pragma unroll
        for (int mh = 0; mh < 2; mh++) {
            const int m = wm * 32 + mh * 16 + g;
#pragma unroll
            for (int nt = 0; nt < 8; nt++) {
                int n = wn * 64 + nt * 8 + t2;
                h1[m * 129 + n]           = fmaxf(d[mh][nt][0] + biasS[n], 0.f);
                h1[m * 129 + n + 1]       = fmaxf(d[mh][nt][1] + biasS[n + 1], 0.f);
                h1[(m + 8) * 129 + n]     = fmaxf(d[mh][nt][2] + biasS[n], 0.f);
                h1[(m + 8) * 129 + n + 1] = fmaxf(d[mh][nt][3] + biasS[n + 1], 0.f);
            }
        }
    }
    __syncthreads();

    // layer2: 128 boards x 64 outs (32 policy | 32 value)
#pragma unroll 1
    for (int it = 0; it < 32; it++) {
        int idx = it * 256 + tid;
        int bd = idx >> 6, o = idx & 63;
        int oo = o & 31;
        const float* h1b  = h1 + bd * 129 + ((o < 32) ? 0 : 64);
        const float* wmat = (o < 32) ? pw2 : vw2;
        float s = (o < 32) ? pb2[oo] : vb2[oo];
#pragma unroll 8
        for (int k = 0; k < 64; k++) s += h1b[k] * wmat[k * 32 + oo];
        h2[bd * 65 + o] = fmaxf(s, 0.f);
    }
    __syncthreads();

    // layer3 + softmax / tanh
    if (tid < 128) {
        int gb = m0 + tid;
        const float* hp = h2 + tid * 65;
        float lg[7];
#pragma unroll
        for (int j = 0; j < 7; j++) {
            float s = pb3[j];
#pragma unroll
            for (int k = 0; k < 32; k++) s += hp[k] * pw3[k * 7 + j];
            lg[j] = s;
        }
        float mx = lg[0];
#pragma unroll
        for (int j = 1; j < 7; j++) mx = fmaxf(mx, lg[j]);
        float se = 0.f;
#pragma unroll
        for (int j = 0; j < 7; j++) { lg[j] = expf(lg[j] - mx); se += lg[j]; }
        float inv = 1.f / se;
#pragma unroll
        for (int j = 0; j < 7; j++) out[(size_t)gb * 7 + j] = lg[j] * inv;

        float v = vb3[0];
#pragma unroll
        for (int k = 0; k < 32; k++) v += hp[32 + k] * vw3[k];
        out[(size_t)BATCH * 7 + gb] = tanhf(v);
    }
}

// =========================================================================
extern "C" void kernel_launch(void* const* d_in, const int* in_sizes, int n_in,
                              void* d_out, int out_size)
{
    const float* x        = (const float*)d_in[0];
    const float* conv_w   = (const float*)d_in[1];
    /* conv_b cancels through batch-norm */
    const float* bn_gamma = (const float*)d_in[3];
    const float* bn_beta  = (const float*)d_in[4];
    const float* pw1 = (const float*)d_in[5];
    const float* pb1 = (const float*)d_in[6];
    const float* pw2 = (const float*)d_in[7];
    const float* pb2 = (const float*)d_in[8];
    const float* pw3 = (const float*)d_in[9];
    const float* pb3 = (const float*)d_in[10];
    const float* vw1 = (const float*)d_in[11];
    const float* vb1 = (const float*)d_in[12];
    const float* vw2 = (const float*)d_in[13];
    const float* vb2 = (const float*)d_in[14];
    const float* vw3 = (const float*)d_in[15];
    const float* vb3 = (const float*)d_in[16];
    float* out = (float*)d_out;

    cudaFuncSetAttribute(k_fused, cudaFuncAttributeMaxDynamicSharedMemorySize, SMEM_DYN);

    k_moments<<<NBLK_MOM, 256>>>(x);
    k_finalize<<<1, 256>>>(conv_w, bn_gamma, bn_beta);
    k_prep<<<128, 256>>>(pw1, vw1);
    k_fused<<<BATCH / 128, 256, SMEM_DYN>>>(x, pb1, vb1, pw2, pb2, pw3, pb3,
                                            vw2, vb2, vw3, vb3, out);
}